// round 10
// baseline (speedup 1.0000x reference)
#include <cuda_runtime.h>
#include <math.h>

#define B_  64
#define LQ  32
#define O_  128
#define LK  256
#define D_  128
#define FULLM 0xffffffffu
#define GRID_N 296        // 2 * 148 SMs: one full wave at occupancy 2

__device__ int g_ctr;     // work-steal counter (zero-init; reset at kernel end)
__device__ int g_done;    // blocks finished (reset at kernel end)

__device__ __forceinline__ bool mask_at(const void* buf, int idx, int mode) {
    if (mode == 0) return ((const int*)buf)[idx] != 0;
    if (mode == 2) return ((const float*)buf)[idx] != 0.0f;
    return ((const unsigned char*)buf)[idx] != 0;
}

// ---- f32x2 packed helpers -------------------------------------------------
__device__ __forceinline__ unsigned long long pk2(float a, float b) {
    unsigned long long r;
    asm("mov.b64 %0,{%1,%2};" : "=l"(r) : "f"(a), "f"(b));
    return r;
}
__device__ __forceinline__ void fma2(unsigned long long& d,
                                     unsigned long long a, unsigned long long b) {
    asm("fma.rn.f32x2 %0,%1,%2,%0;" : "+l"(d) : "l"(a), "l"(b));
}
__device__ __forceinline__ float2 upk2(unsigned long long v) {
    float2 r;
    asm("mov.b64 {%0,%1},%2;" : "=f"(r.x), "=f"(r.y) : "l"(v));
    return r;
}

// ---------------------------------------------------------------------------
// Grid = 296 x 256 threads, work-stealing over (active b) x 128 o items.
// Warp w: wg = w>>2 picks d-half of each 32-d chunk; i rows = (w&3)*8 .. +8.
// Lane l owns 8 j: {4l..4l+3} and {128+4l..128+4l+3}. acc[8][4] f32x2.
// wg1's partial accs combined into wg0 via retired kt buffer; wg0 epilogue.
// ---------------------------------------------------------------------------
__global__ __launch_bounds__(256, 2)
void fused_score_kernel(const float* __restrict__ q,
                        const float* __restrict__ k,
                        const void* __restrict__ q_mask,
                        const void* __restrict__ k_mask,
                        const float* __restrict__ logit_scale,
                        float* __restrict__ out) {
    const int tid = threadIdx.x;
    const int w   = tid >> 5, l = tid & 31;

    __shared__ int   s_nact, s_item;
    __shared__ unsigned char s_blist[B_];
    __shared__ unsigned char s_act[B_];
    extern __shared__ float smem[];
    float* q_s  = smem;              // 4096
    float* kt   = q_s + LQ * D_;     // 8192 (swizzled [d][j]; reused as combine scratch)
    float* ivk  = kt + 32 * LK;      // 256
    float* wm   = ivk + LK;          // 256
    float* ivq  = wm + LK;           // 32
    float* red  = ivq + LQ;          // 8

    // ---- Phase A: dtype sniff + active flags + compact list ----
    int mode;
    {
        unsigned word = ((const unsigned*)q_mask)[l];   // first 128B safe for all dtypes
        unsigned bi = __ballot_sync(FULLM, word <= 1u);
        unsigned bf = __ballot_sync(FULLM, word == 0u || word == 0x3F800000u);
        mode = (bi == FULLM) ? 0 : (bf == FULLM) ? 2 : 1;
    }
    {
        int bb = tid >> 2, sub = tid & 3;
        int any = 0;
        #pragma unroll
        for (int e = 0; e < 8; e++)
            any |= mask_at(q_mask, bb * LQ + sub * 8 + e, mode) ? 1 : 0;
        any |= __shfl_xor_sync(FULLM, any, 1);
        any |= __shfl_xor_sync(FULLM, any, 2);
        if ((l & 3) == 0) s_act[bb] = (any == 0);
    }
    __syncthreads();
    if (w == 0) {
        unsigned f0 = __ballot_sync(FULLM, s_act[l] != 0);
        unsigned f1 = __ballot_sync(FULLM, s_act[32 + l] != 0);
        int n0 = __popc(f0);
        if (f0 & (1u << l)) s_blist[__popc(f0 & ((1u << l) - 1u))] = (unsigned char)l;
        if (f1 & (1u << l)) s_blist[n0 + __popc(f1 & ((1u << l) - 1u))] = (unsigned char)(32 + l);
        if (l == 0) s_nact = n0 + __popc(f1);
    }
    if (blockIdx.x < B_ && tid < O_) {
        if (!s_act[blockIdx.x]) out[blockIdx.x * O_ + tid] = 0.0f;
    }
    __syncthreads();
    const int n_items = s_nact * O_;

    const int g = tid >> 3, d4 = tid & 7;
    const int wg  = w >> 2;          // d-half selector
    const int ihw = (w & 3) * 8;     // i rows

    // ---- work-steal loop ----
    for (;;) {
        __syncthreads();             // also protects smem reuse across items
        if (tid == 0) s_item = atomicAdd(&g_ctr, 1);
        __syncthreads();
        const int t = s_item;
        if (t >= n_items) break;
        const int b = s_blist[t >> 7];
        const int o = t & (O_ - 1);

        // stage q tile + k-mask weights
        {
            const float4* q4 = (const float4*)(q + (size_t)b * LQ * D_);
            #pragma unroll
            for (int it = 0; it < 4; it++)
                ((float4*)q_s)[it * 256 + tid] = q4[it * 256 + tid];
            wm[tid] = mask_at(k_mask, o * LK + tid, mode) ? 0.0f : 1.0f;
        }
        __syncthreads();
        {   // warp w: invq for rows w*4 .. w*4+3
            #pragma unroll
            for (int r = 0; r < 4; r++) {
                int row = w * 4 + r;
                float s = q_s[row * D_ + l] * q_s[row * D_ + l]
                        + q_s[row * D_ + l + 32] * q_s[row * D_ + l + 32]
                        + q_s[row * D_ + l + 64] * q_s[row * D_ + l + 64]
                        + q_s[row * D_ + l + 96] * q_s[row * D_ + l + 96];
                #pragma unroll
                for (int of = 16; of; of >>= 1) s += __shfl_xor_sync(FULLM, s, of);
                if (l == 0) ivq[row] = 1.0f / fmaxf(sqrtf(s), 1e-12f);
            }
        }

        unsigned long long acc[8][4];
        #pragma unroll
        for (int ii = 0; ii < 8; ii++)
            #pragma unroll
            for (int p = 0; p < 4; p++) acc[ii][p] = 0ull;
        float ksq[8];
        #pragma unroll
        for (int t8 = 0; t8 < 8; t8++) ksq[t8] = 0.0f;

        const float4* kr4 = (const float4*)(k + (size_t)o * LK * D_);

        #pragma unroll 1
        for (int c = 0; c < 4; c++) {
            __syncthreads();
            #pragma unroll
            for (int t8 = 0; t8 < 8; t8++) {
                int j = t8 * 32 + g;
                float4 v = kr4[j * (D_ / 4) + c * 8 + d4];
                ksq[t8] += v.x * v.x + v.y * v.y + v.z * v.z + v.w * v.w;
                int col = (((j >> 2) ^ d4) << 2) + (j & 3);
                kt[(4 * d4 + 0) * LK + col] = v.x;
                kt[(4 * d4 + 1) * LK + col] = v.y;
                kt[(4 * d4 + 2) * LK + col] = v.z;
                kt[(4 * d4 + 3) * LK + col] = v.w;
            }
            __syncthreads();

            const int dbase = wg * 16;   // this warp-group's d-half of the chunk
            #pragma unroll
            for (int d2 = 0; d2 < 8; d2++) {
                const int ld0 = dbase + 2 * d2;
                unsigned long long ka[4], kb[4];
                {
                    int s0 = (ld0 >> 2) & 7;
                    const float* r0 = kt + ld0 * LK;
                    float4 a  = *(const float4*)(r0 + ((l ^ s0) << 2));
                    float4 b4 = *(const float4*)(r0 + 128 + ((l ^ s0) << 2));
                    ka[0] = pk2(a.x, a.y);  ka[1] = pk2(a.z, a.w);
                    ka[2] = pk2(b4.x, b4.y); ka[3] = pk2(b4.z, b4.w);
                    int s1 = ((ld0 + 1) >> 2) & 7;
                    const float* r1 = kt + (ld0 + 1) * LK;
                    float4 c4 = *(const float4*)(r1 + ((l ^ s1) << 2));
                    float4 e4 = *(const float4*)(r1 + 128 + ((l ^ s1) << 2));
                    kb[0] = pk2(c4.x, c4.y); kb[1] = pk2(c4.z, c4.w);
                    kb[2] = pk2(e4.x, e4.y); kb[3] = pk2(e4.z, e4.w);
                }
                #pragma unroll
                for (int ii = 0; ii < 8; ii++) {
                    float2 qv = *(const float2*)(q_s + (ihw + ii) * D_ + c * 32 + ld0);
                    unsigned long long q0 = pk2(qv.x, qv.x);
                    unsigned long long q1 = pk2(qv.y, qv.y);
                    #pragma unroll
                    for (int p = 0; p < 4; p++) fma2(acc[ii][p], q0, ka[p]);
                    #pragma unroll
                    for (int p = 0; p < 4; p++) fma2(acc[ii][p], q1, kb[p]);
                }
            }
        }

        // invk from ksq (octet reduce across d4)
        #pragma unroll
        for (int t8 = 0; t8 < 8; t8++) {
            float s = ksq[t8];
            s += __shfl_xor_sync(FULLM, s, 1);
            s += __shfl_xor_sync(FULLM, s, 2);
            s += __shfl_xor_sync(FULLM, s, 4);
            if (d4 == 0) ivk[t8 * 32 + g] = s;
        }
        __syncthreads();
        float myinv = 1.0f / fmaxf(sqrtf(ivk[tid]), 1e-12f);
        __syncthreads();
        ivk[tid] = myinv;
        __syncthreads();

        // combine d-halves: wg1 -> scratch (kt, retired), wg0 adds + epilogue
        unsigned long long* scr = (unsigned long long*)kt;
        if (wg == 1) {
            int base = ((w & 3) * 32 + l) * 32;
            #pragma unroll
            for (int ii = 0; ii < 8; ii++)
                #pragma unroll
                for (int p = 0; p < 4; p++) scr[base + ii * 4 + p] = acc[ii][p];
        }
        __syncthreads();
        if (wg == 0) {
            int base = ((w & 3) * 32 + l) * 32;
            float4 iva = *(const float4*)(ivk + 4 * l);
            float4 ivb = *(const float4*)(ivk + 128 + 4 * l);
            float4 wma = *(const float4*)(wm + 4 * l);
            float4 wmb = *(const float4*)(wm + 128 + 4 * l);
            float lsum = 0.0f;
            #pragma unroll
            for (int ii = 0; ii < 8; ii++) {
                float2 m0 = upk2(acc[ii][0]), o0 = upk2(scr[base + ii * 4 + 0]);
                float2 m1 = upk2(acc[ii][1]), o1 = upk2(scr[base + ii * 4 + 1]);
                float2 m2 = upk2(acc[ii][2]), o2 = upk2(scr[base + ii * 4 + 2]);
                float2 m3 = upk2(acc[ii][3]), o3 = upk2(scr[base + ii * 4 + 3]);
                float a12 = 12.0f * ivq[ihw + ii];
                float p = wma.x * __expf(a12 * iva.x * (m0.x + o0.x))
                        + wma.y * __expf(a12 * iva.y * (m0.y + o0.y))
                        + wma.z * __expf(a12 * iva.z * (m1.x + o1.x))
                        + wma.w * __expf(a12 * iva.w * (m1.y + o1.y))
                        + wmb.x * __expf(a12 * ivb.x * (m2.x + o2.x))
                        + wmb.y * __expf(a12 * ivb.y * (m2.y + o2.y))
                        + wmb.z * __expf(a12 * ivb.z * (m3.x + o3.x))
                        + wmb.w * __expf(a12 * ivb.w * (m3.y + o3.y));
                #pragma unroll
                for (int of = 16; of; of >>= 1) p += __shfl_xor_sync(FULLM, p, of);
                if (l == 0) lsum += __logf(p);   // -inf if all j masked
            }
            if (l == 0) red[w] = lsum;
        }
        __syncthreads();
        if (tid == 0) {
            float tt = red[0] + red[1] + red[2] + red[3];
            float s = tt * (1.0f / 12.0f);
            s = s / (sqrtf((float)(LQ * LK)) + 1e-6f);
            s *= fminf(expf(logit_scale[0]), 100.0f);
            if (!isfinite(s)) s = 0.0f;
            out[b * O_ + o] = s;
        }
    }

    // ---- reset work-steal counters for next graph replay ----
    if (tid == 0) {
        __threadfence();
        int d = atomicAdd(&g_done, 1);
        if (d == (int)gridDim.x - 1) {
            g_ctr = 0;
            g_done = 0;
            __threadfence();
        }
    }
}

// ---------------------------------------------------------------------------
extern "C" void kernel_launch(void* const* d_in, const int* in_sizes, int n_in,
                              void* d_out, int out_size) {
    const float* q  = (const float*)d_in[0];
    const float* k  = (const float*)d_in[1];
    const void*  qm = d_in[2];
    const void*  km = d_in[3];
    const float* ls = (const float*)d_in[4];
    float* out = (float*)d_out;

    const int smem_bytes =
        (LQ * D_ + 32 * LK + LK + LK + LQ + 8) * (int)sizeof(float);  // ~51.4KB
    cudaFuncSetAttribute(fused_score_kernel,
                         cudaFuncAttributeMaxDynamicSharedMemorySize,
                         smem_bytes);
    fused_score_kernel<<<GRID_N, 256, smem_bytes>>>(q, k, qm, km, ls, out);
}

// round 11
// speedup vs baseline: 1.0862x; 1.0862x over previous
#include <cuda_runtime.h>
#include <math.h>

#define B_  64
#define LQ  32
#define O_  128
#define LK  256
#define D_  128
#define FULLM 0xffffffffu
#define GRID_N 592        // 2 waves at occupancy 2 on 148 SMs

__device__ __forceinline__ bool mask_at(const void* buf, int idx, int mode) {
    if (mode == 0) return ((const int*)buf)[idx] != 0;
    if (mode == 2) return ((const float*)buf)[idx] != 0.0f;
    return ((const unsigned char*)buf)[idx] != 0;
}

// ---- f32x2 packed helpers -------------------------------------------------
__device__ __forceinline__ unsigned long long pk2(float a, float b) {
    unsigned long long r;
    asm("mov.b64 %0,{%1,%2};" : "=l"(r) : "f"(a), "f"(b));
    return r;
}
__device__ __forceinline__ void fma2(unsigned long long& d,
                                     unsigned long long a, unsigned long long b) {
    asm("fma.rn.f32x2 %0,%1,%2,%0;" : "+l"(d) : "l"(a), "l"(b));
}
__device__ __forceinline__ float2 upk2(unsigned long long v) {
    float2 r;
    asm("mov.b64 {%0,%1},%2;" : "=f"(r.x), "=f"(r.y) : "l"(v));
    return r;
}

// ---------------------------------------------------------------------------
// Grid = 592 x 256 threads; item = (active b, o), static item = blockIdx.x
// (strided loop for safety when n_items > grid).
// q stored PRE-DUPLICATED in smem: q2[i][d] = (q_id, q_id) f32x2 -> mainloop
// q operand is one broadcast LDS.64, zero packing MOVs.
// Warp w: jhalf = w&1 (j base 0/128), i rows ihw=(w>>1)*8 .. +8.
// Lane l owns j = jhalf*128 + 4l..4l+3; acc[8][2] f32x2 (32 regs).
// kt chunk transpose + swizzle + in-flight ksq: unchanged from R9 (verified).
// ---------------------------------------------------------------------------
__global__ __launch_bounds__(256, 2)
void fused_score_kernel(const float* __restrict__ q,
                        const float* __restrict__ k,
                        const void* __restrict__ q_mask,
                        const void* __restrict__ k_mask,
                        const float* __restrict__ logit_scale,
                        float* __restrict__ out) {
    const int tid = threadIdx.x;
    const int w   = tid >> 5, l = tid & 31;

    __shared__ int s_nact;
    __shared__ unsigned char s_blist[B_];
    __shared__ unsigned char s_act[B_];
    extern __shared__ float smem[];
    unsigned long long* q2 = (unsigned long long*)smem;    // 4096 u64 = 32KB
    float* kt  = smem + 2 * LQ * D_;    // 8192 f = 32KB (swizzled [d][j] chunk)
    float* ivk = kt + 32 * LK;          // 256
    float* wm  = ivk + LK;              // 256
    float* ivq = wm + LK;               // 32
    float* red = ivq + LQ;              // 64

    // ---- Phase A: dtype sniff + active flags + compact list ----
    int mode;
    {
        unsigned word = ((const unsigned*)q_mask)[l];   // first 128B safe all dtypes
        unsigned bi = __ballot_sync(FULLM, word <= 1u);
        unsigned bf = __ballot_sync(FULLM, word == 0u || word == 0x3F800000u);
        mode = (bi == FULLM) ? 0 : (bf == FULLM) ? 2 : 1;
    }
    {
        int bb = tid >> 2, sub = tid & 3;
        int any = 0;
        #pragma unroll
        for (int e = 0; e < 8; e++)
            any |= mask_at(q_mask, bb * LQ + sub * 8 + e, mode) ? 1 : 0;
        any |= __shfl_xor_sync(FULLM, any, 1);
        any |= __shfl_xor_sync(FULLM, any, 2);
        if ((l & 3) == 0) s_act[bb] = (any == 0);
    }
    __syncthreads();
    if (w == 0) {
        unsigned f0 = __ballot_sync(FULLM, s_act[l] != 0);
        unsigned f1 = __ballot_sync(FULLM, s_act[32 + l] != 0);
        int n0 = __popc(f0);
        if (f0 & (1u << l)) s_blist[__popc(f0 & ((1u << l) - 1u))] = (unsigned char)l;
        if (f1 & (1u << l)) s_blist[n0 + __popc(f1 & ((1u << l) - 1u))] = (unsigned char)(32 + l);
        if (l == 0) s_nact = n0 + __popc(f1);
    }
    if (blockIdx.x < B_ && tid < O_) {
        if (!s_act[blockIdx.x]) out[blockIdx.x * O_ + tid] = 0.0f;
    }
    __syncthreads();
    const int n_items = s_nact * O_;

    const int g = tid >> 3, d4 = tid & 7;
    const int jhalf = w & 1, ihw = (w >> 1) * 8;

    for (int item = blockIdx.x; item < n_items; item += GRID_N) {
        const int b = s_blist[item >> 7];
        const int o = item & (O_ - 1);

        // ---- stage q pre-duplicated + k-mask weights ----
        {
            const float2* qg = (const float2*)(q + (size_t)b * LQ * D_);
            #pragma unroll
            for (int t = 0; t < 8; t++) {
                int idx = t * 256 + tid;          // 2048 float2 total
                float2 v = qg[idx];               // coalesced
                q2[2 * idx]     = pk2(v.x, v.x);  // q2[i*128 + d], dup'd
                q2[2 * idx + 1] = pk2(v.y, v.y);
            }
            wm[tid] = mask_at(k_mask, o * LK + tid, mode) ? 0.0f : 1.0f;
        }
        __syncthreads();
        {   // warp w: invq for rows w*4 .. w*4+3 (read dup'd pairs, use .x)
            #pragma unroll
            for (int r = 0; r < 4; r++) {
                int row = w * 4 + r;
                float s = 0.0f;
                #pragma unroll
                for (int qd = 0; qd < 4; qd++) {
                    float2 u = upk2(q2[row * D_ + qd * 32 + l]);
                    s += u.x * u.x;
                }
                #pragma unroll
                for (int of = 16; of; of >>= 1) s += __shfl_xor_sync(FULLM, s, of);
                if (l == 0) ivq[row] = 1.0f / fmaxf(sqrtf(s), 1e-12f);
            }
        }

        unsigned long long acc[8][2];
        #pragma unroll
        for (int ii = 0; ii < 8; ii++) { acc[ii][0] = 0ull; acc[ii][1] = 0ull; }
        float ksq[8];
        #pragma unroll
        for (int t8 = 0; t8 < 8; t8++) ksq[t8] = 0.0f;

        const float4* kr4 = (const float4*)(k + (size_t)o * LK * D_);

        #pragma unroll 1
        for (int c = 0; c < 4; c++) {
            __syncthreads();
            #pragma unroll
            for (int t8 = 0; t8 < 8; t8++) {      // transpose chunk (verified)
                int j = t8 * 32 + g;
                float4 v = kr4[j * (D_ / 4) + c * 8 + d4];
                ksq[t8] += v.x * v.x + v.y * v.y + v.z * v.z + v.w * v.w;
                int col = (((j >> 2) ^ d4) << 2) + (j & 3);
                kt[(4 * d4 + 0) * LK + col] = v.x;
                kt[(4 * d4 + 1) * LK + col] = v.y;
                kt[(4 * d4 + 2) * LK + col] = v.z;
                kt[(4 * d4 + 3) * LK + col] = v.w;
            }
            __syncthreads();

            const unsigned long long* q2b = q2 + c * 32;   // d offset in row
            #pragma unroll 4
            for (int d = 0; d < 32; d++) {
                int s0 = (d >> 2) & 7;
                const float* r0 = kt + d * LK + jhalf * 128;
                float4 a = *(const float4*)(r0 + ((l ^ s0) << 2));
                unsigned long long kp0 = pk2(a.x, a.y);
                unsigned long long kp1 = pk2(a.z, a.w);
                #pragma unroll
                for (int ii = 0; ii < 8; ii++) {
                    unsigned long long qd = q2b[(ihw + ii) * D_ + d];  // bcast LDS.64
                    fma2(acc[ii][0], qd, kp0);
                    fma2(acc[ii][1], qd, kp1);
                }
            }
        }

        // ---- invk from ksq (octet reduce across d4) ----
        #pragma unroll
        for (int t8 = 0; t8 < 8; t8++) {
            float s = ksq[t8];
            s += __shfl_xor_sync(FULLM, s, 1);
            s += __shfl_xor_sync(FULLM, s, 2);
            s += __shfl_xor_sync(FULLM, s, 4);
            if (d4 == 0) ivk[t8 * 32 + g] = s;
        }
        __syncthreads();
        float myinv = 1.0f / fmaxf(sqrtf(ivk[tid]), 1e-12f);
        __syncthreads();
        ivk[tid] = myinv;
        __syncthreads();

        // ---- epilogue (R9 pattern) ----
        float4 iva = *(const float4*)(ivk + jhalf * 128 + 4 * l);
        float4 wma = *(const float4*)(wm + jhalf * 128 + 4 * l);
        #pragma unroll
        for (int ii = 0; ii < 8; ii++) {
            float a12 = 12.0f * ivq[ihw + ii];
            float2 f0 = upk2(acc[ii][0]), f1 = upk2(acc[ii][1]);
            float p = wma.x * __expf(a12 * iva.x * f0.x)
                    + wma.y * __expf(a12 * iva.y * f0.y)
                    + wma.z * __expf(a12 * iva.z * f1.x)
                    + wma.w * __expf(a12 * iva.w * f1.y);
            #pragma unroll
            for (int of = 16; of; of >>= 1) p += __shfl_xor_sync(FULLM, p, of);
            if (l == 0) red[(ihw + ii) * 2 + jhalf] = p;
        }
        __syncthreads();

        if (tid < 32) {
            float p = red[2 * tid] + red[2 * tid + 1];
            float lse = __logf(p);                    // -inf if all j masked
            #pragma unroll
            for (int of = 16; of; of >>= 1) lse += __shfl_xor_sync(FULLM, lse, of);
            if (tid == 0) {
                float s = lse * (1.0f / 12.0f);
                s = s / (sqrtf((float)(LQ * LK)) + 1e-6f);
                s *= fminf(expf(logit_scale[0]), 100.0f);
                if (!isfinite(s)) s = 0.0f;
                out[b * O_ + o] = s;
            }
        }
        __syncthreads();   // protect smem reuse across items
    }
}

// ---------------------------------------------------------------------------
extern "C" void kernel_launch(void* const* d_in, const int* in_sizes, int n_in,
                              void* d_out, int out_size) {
    const float* q  = (const float*)d_in[0];
    const float* k  = (const float*)d_in[1];
    const void*  qm = d_in[2];
    const void*  km = d_in[3];
    const float* ls = (const float*)d_in[4];
    float* out = (float*)d_out;

    const int smem_bytes =
        (2 * LQ * D_ + 32 * LK + LK + LK + LQ + 64) * (int)sizeof(float); // ~68KB
    cudaFuncSetAttribute(fused_score_kernel,
                         cudaFuncAttributeMaxDynamicSharedMemorySize,
                         smem_bytes);
    fused_score_kernel<<<GRID_N, 256, smem_bytes>>>(q, k, qm, km, ls, out);
}